// round 1
// baseline (speedup 1.0000x reference)
#include <cuda_runtime.h>
#include <cuda_bf16.h>
#include <cstdint>

// ---------------- problem constants ----------------
#define NN      65536
#define CC      256
#define BB      8
#define EMBD    512
#define NET     7          // edge types
#define EE      458752     // NN * 7
#define WROW    263        // C + N_NODE_TYPE
#define EPSV    1e-5f

// ---------------- device scratch ----------------
__device__ float    g_Y[(size_t)NET * NN * CC];   // 470 MB: Y_t = h @ W_t
__device__ float    g_out1[(size_t)NN * CC];      // h after conv1 + emb
__device__ float    g_h[(size_t)NN * CC];         // silu(groupnorm(.))
__device__ float    g_S1[BB * CC];
__device__ float    g_S2[BB * CC];
__device__ float    g_cnt[BB];
__device__ float    g_mg[BB * 32];
__device__ float    g_istd[BB * 32];
__device__ float    g_emb[BB * CC];
__device__ int      g_deg[NN];
__device__ int      g_off[NN + 1];
__device__ int      g_cur[NN];
__device__ unsigned g_epack[EE];

// ---------------- helpers ----------------
__device__ __forceinline__ unsigned f2tf32(float f) {
    unsigned u;
    asm("cvt.rna.tf32.f32 %0, %1;" : "=r"(u) : "f"(f));
    return u;
}

__device__ __forceinline__ void mma_tf32(float c[4], unsigned a0, unsigned a1,
                                         unsigned a2, unsigned a3,
                                         unsigned b0, unsigned b1) {
    asm volatile(
        "mma.sync.aligned.m16n8k8.row.col.f32.tf32.tf32.f32 "
        "{%0,%1,%2,%3}, {%4,%5,%6,%7}, {%8,%9}, {%0,%1,%2,%3};\n"
        : "+f"(c[0]), "+f"(c[1]), "+f"(c[2]), "+f"(c[3])
        : "r"(a0), "r"(a1), "r"(a2), "r"(a3), "r"(b0), "r"(b1));
}

__device__ __forceinline__ float silu(float y) {
    return y / (1.f + __expf(-y));
}

// ---------------- kernels ----------------

// zero stats + degree counters
__global__ void k_zero_all() {
    int i = blockIdx.x * blockDim.x + threadIdx.x;
    if (i < NN)        g_deg[i] = 0;
    if (i < BB * CC)   { g_S1[i] = 0.f; g_S2[i] = 0.f; }
    if (i < BB)        g_cnt[i] = 0.f;
}

__global__ void k_zero_stats() {
    int i = blockIdx.x * blockDim.x + threadIdx.x;
    if (i < BB * CC) { g_S1[i] = 0.f; g_S2[i] = 0.f; }
}

// edge degree count (by destination row)
__global__ void k_deg(const int* __restrict__ ei) {
    int e = blockIdx.x * blockDim.x + threadIdx.x;
    if (e < EE) atomicAdd(&g_deg[ei[e]], 1);
}

// single-block exclusive scan of 65536 degrees
__global__ void k_scan() {
    __shared__ int ps[1024];
    int t = threadIdx.x;
    int s = 0;
#pragma unroll 8
    for (int i = 0; i < 64; i++) s += g_deg[t * 64 + i];
    ps[t] = s;
    __syncthreads();
    for (int off = 1; off < 1024; off <<= 1) {
        int v = (t >= off) ? ps[t - off] : 0;
        __syncthreads();
        ps[t] += v;
        __syncthreads();
    }
    int run = (t == 0) ? 0 : ps[t - 1];
    for (int i = 0; i < 64; i++) {
        int d = g_deg[t * 64 + i];
        g_off[t * 64 + i] = run;
        g_cur[t * 64 + i] = run;
        run += d;
    }
    if (t == 1023) g_off[NN] = run;
}

// scatter edges into CSR slots; payload = col | etype<<16 | ntype(col)<<19
__global__ void k_fill(const int* __restrict__ ei, const int* __restrict__ et,
                       const int* __restrict__ ntp) {
    int e = blockIdx.x * blockDim.x + threadIdx.x;
    if (e >= EE) return;
    int r = ei[e];
    int c = ei[EE + e];
    int t = et[e];
    int nt = ntp[c];
    int pos = atomicAdd(&g_cur[r], 1);
    g_epack[pos] = (unsigned)c | ((unsigned)t << 16) | ((unsigned)nt << 19);
}

// emb_out = silu(emb) @ emb_w + emb_b   [8, 256]
__global__ void k_emb(const float* __restrict__ emb, const float* __restrict__ ew,
                      const float* __restrict__ eb) {
    __shared__ float se[EMBD];
    int b = blockIdx.x;
    int j = threadIdx.x;
    for (int k = j; k < EMBD; k += 256) {
        float v = emb[b * EMBD + k];
        se[k] = silu(v);
    }
    __syncthreads();
    float acc = eb[j];
#pragma unroll 8
    for (int k = 0; k < EMBD; k++) acc = fmaf(se[k], ew[k * CC + j], acc);
    g_emb[b * CC + j] = acc;
}

// per-(batch, channel) sum & sumsq; batch_id is sorted so <=2 flushes per 64-row chunk
__global__ void k_stats(const float* __restrict__ src, int use_out1,
                        const int* __restrict__ bid, int do_cnt) {
    const float* s = use_out1 ? g_out1 : src;
    int c = threadIdx.x;
    int r0 = blockIdx.x * 64;
    float s1 = 0.f, s2 = 0.f;
    int cb = bid[r0];
    int cl = 0;
    for (int i = 0; i < 64; i++) {
        int r = r0 + i;
        int b = bid[r];
        if (b != cb) {
            atomicAdd(&g_S1[cb * CC + c], s1);
            atomicAdd(&g_S2[cb * CC + c], s2);
            if (do_cnt && c == 0) atomicAdd(&g_cnt[cb], (float)cl);
            s1 = 0.f; s2 = 0.f; cl = 0; cb = b;
        }
        float v = s[(size_t)r * CC + c];
        s1 += v;
        s2 = fmaf(v, v, s2);
        cl++;
    }
    atomicAdd(&g_S1[cb * CC + c], s1);
    atomicAdd(&g_S2[cb * CC + c], s2);
    if (do_cnt && c == 0) atomicAdd(&g_cnt[cb], (float)cl);
}

// group means / inv_std:  group = channel>>3 (cpg = 8), 32 groups
__global__ void k_fin() {
    int t = threadIdx.x;          // 256 threads = 8 batches x 32 groups
    int b = t >> 5, g = t & 31;
    float gs1 = 0.f, gs2 = 0.f;
#pragma unroll
    for (int i = 0; i < 8; i++) {
        gs1 += g_S1[b * CC + g * 8 + i];
        gs2 += g_S2[b * CC + g * 8 + i];
    }
    float n = g_cnt[b] * 8.f;
    float inv = 1.f / (n + EPSV);
    float m = gs1 * inv;
    float var = (gs2 - 2.f * m * gs1 + n * m * m) * inv;
    g_mg[b * 32 + g] = m;
    g_istd[b * 32 + g] = rsqrtf(var + EPSV);
}

// h = silu( (src - m_g) * istd_g * w + b )
__global__ void k_norm(const float* __restrict__ src, int use_out1,
                       const int* __restrict__ bid, const float* __restrict__ w,
                       const float* __restrict__ bb) {
    const float* s = use_out1 ? g_out1 : src;
    int n = blockIdx.x;
    int ch = threadIdx.x;
    int b = bid[n];
    int g = ch >> 3;
    float m = g_mg[b * 32 + g];
    float is = g_istd[b * 32 + g];
    float v = s[(size_t)n * CC + ch];
    float y = (v - m) * is * w[ch] + bb[ch];
    g_h[(size_t)n * CC + ch] = silu(y);
}

// Y_t = h @ W_t   (tf32 mma.sync; block tile 128x128, 7 types, K=256)
// grid: x = 14 (2 ntiles x 7 types), y = 512 mtiles  -> A-tile L2 reuse across x
__global__ void __launch_bounds__(256) k_gemm(const float* __restrict__ W) {
    __shared__ unsigned sA[128][33];
    __shared__ unsigned sB[32][132];

    int ntile = blockIdx.x & 1;
    int t = blockIdx.x >> 1;
    int m0 = blockIdx.y * 128;
    int n0 = ntile * 128;

    int tid = threadIdx.x;
    int lane = tid & 31, warp = tid >> 5;
    int wm = warp & 3, wn = warp >> 2;      // warp grid 4x2 -> 32x64 per warp
    int gid = lane >> 2, tig = lane & 3;

    float c[2][8][4];
#pragma unroll
    for (int mm = 0; mm < 2; mm++)
#pragma unroll
        for (int nn = 0; nn < 8; nn++)
#pragma unroll
            for (int q = 0; q < 4; q++) c[mm][nn][q] = 0.f;

    const float* Abase = g_h + (size_t)m0 * CC;
    const float* Bbase = W + (size_t)t * WROW * CC + n0;

    int ar = tid & 127, ah = tid >> 7;       // A: 128 rows x 32 cols per kb
    int bk = tid >> 3, bj = (tid & 7) * 16;  // B: 32 rows  x 128 cols per kb

    for (int kb = 0; kb < 8; kb++) {
#pragma unroll
        for (int q = 0; q < 4; q++) {
            float4 v = *(const float4*)(Abase + (size_t)ar * CC + kb * 32 + ah * 16 + q * 4);
            int cb = ah * 16 + q * 4;
            sA[ar][cb + 0] = f2tf32(v.x);
            sA[ar][cb + 1] = f2tf32(v.y);
            sA[ar][cb + 2] = f2tf32(v.z);
            sA[ar][cb + 3] = f2tf32(v.w);
        }
#pragma unroll
        for (int q = 0; q < 4; q++) {
            float4 v = *(const float4*)(Bbase + (size_t)(kb * 32 + bk) * CC + bj + q * 4);
            sB[bk][bj + q * 4 + 0] = f2tf32(v.x);
            sB[bk][bj + q * 4 + 1] = f2tf32(v.y);
            sB[bk][bj + q * 4 + 2] = f2tf32(v.z);
            sB[bk][bj + q * 4 + 3] = f2tf32(v.w);
        }
        __syncthreads();
#pragma unroll
        for (int kk = 0; kk < 4; kk++) {
            unsigned a[2][4];
#pragma unroll
            for (int mm = 0; mm < 2; mm++) {
                int r = wm * 32 + mm * 16 + gid;
                a[mm][0] = sA[r][kk * 8 + tig];
                a[mm][1] = sA[r + 8][kk * 8 + tig];
                a[mm][2] = sA[r][kk * 8 + tig + 4];
                a[mm][3] = sA[r + 8][kk * 8 + tig + 4];
            }
#pragma unroll
            for (int nn = 0; nn < 8; nn++) {
                int col = wn * 64 + nn * 8 + gid;
                unsigned b0 = sB[kk * 8 + tig][col];
                unsigned b1 = sB[kk * 8 + tig + 4][col];
                mma_tf32(c[0][nn], a[0][0], a[0][1], a[0][2], a[0][3], b0, b1);
                mma_tf32(c[1][nn], a[1][0], a[1][1], a[1][2], a[1][3], b0, b1);
            }
        }
        __syncthreads();
    }

    float* Yb = g_Y + ((size_t)t * NN + m0) * CC + n0;
#pragma unroll
    for (int mm = 0; mm < 2; mm++) {
#pragma unroll
        for (int nn = 0; nn < 8; nn++) {
            int r = wm * 32 + mm * 16 + gid;
            int cc2 = wn * 64 + nn * 8 + tig * 2;
            float2 v0 = make_float2(c[mm][nn][0], c[mm][nn][1]);
            float2 v1 = make_float2(c[mm][nn][2], c[mm][nn][3]);
            *(float2*)(Yb + (size_t)r * CC + cc2) = v0;
            *(float2*)(Yb + (size_t)(r + 8) * CC + cc2) = v1;
        }
    }
}

// warp-per-node gather:  dst[n] = base + sum_edges ( Y[t][col] + W_onehot[t][nt] )
// final_pass=0: base = emb_out[batch], dst = g_out1; final_pass=1: base = x, dst = d_out
__global__ void k_gather(const float* __restrict__ xbase, const float* __restrict__ W,
                         float* __restrict__ dout, const int* __restrict__ bid,
                         int final_pass) {
    int widx = (blockIdx.x * blockDim.x + threadIdx.x) >> 5;
    int lane = threadIdx.x & 31;
    if (widx >= NN) return;
    int n = widx;
    const float* bp;
    float* dst;
    if (final_pass) {
        bp = xbase + (size_t)n * CC;
        dst = dout + (size_t)n * CC;
    } else {
        bp = g_emb + (size_t)bid[n] * CC;
        dst = g_out1 + (size_t)n * CC;
    }
    float4 a0 = *(const float4*)(bp + lane * 8);
    float4 a1 = *(const float4*)(bp + lane * 8 + 4);
    int e0 = g_off[n], e1 = g_off[n + 1];
    for (int e = e0; e < e1; e++) {
        unsigned p = g_epack[e];
        int c = p & 0xFFFF;
        int t = (p >> 16) & 7;
        int nt = (p >> 19) & 7;
        const float* y = g_Y + ((size_t)t * NN + c) * CC + lane * 8;
        const float* wr = W + (size_t)(t * WROW + CC + nt) * CC + lane * 8;
        float4 y0 = *(const float4*)y;
        float4 y1 = *(const float4*)(y + 4);
        float4 w0 = *(const float4*)wr;
        float4 w1 = *(const float4*)(wr + 4);
        a0.x += y0.x + w0.x; a0.y += y0.y + w0.y;
        a0.z += y0.z + w0.z; a0.w += y0.w + w0.w;
        a1.x += y1.x + w1.x; a1.y += y1.y + w1.y;
        a1.z += y1.z + w1.z; a1.w += y1.w + w1.w;
    }
    *(float4*)(dst + lane * 8) = a0;
    *(float4*)(dst + lane * 8 + 4) = a1;
}

// ---------------- launcher ----------------
extern "C" void kernel_launch(void* const* d_in, const int* in_sizes, int n_in,
                              void* d_out, int out_size) {
    const float* x    = (const float*)d_in[0];
    const float* emb  = (const float*)d_in[1];
    const int*   bid  = (const int*)d_in[2];
    const int*   ei   = (const int*)d_in[3];
    const int*   et   = (const int*)d_in[4];
    const int*   ntp  = (const int*)d_in[5];
    const float* gn1w = (const float*)d_in[6];
    const float* gn1b = (const float*)d_in[7];
    const float* w1   = (const float*)d_in[8];
    const float* embw = (const float*)d_in[9];
    const float* embb = (const float*)d_in[10];
    const float* gn2w = (const float*)d_in[11];
    const float* gn2b = (const float*)d_in[12];
    const float* w2   = (const float*)d_in[13];
    float* out = (float*)d_out;

    // CSR build (shared by both convs) + emb
    k_zero_all<<<(NN + 255) / 256, 256>>>();
    k_deg<<<EE / 256, 256>>>(ei);
    k_scan<<<1, 1024>>>();
    k_fill<<<EE / 256, 256>>>(ei, et, ntp);
    k_emb<<<BB, 256>>>(emb, embw, embb);

    // block 1: gn1 + silu + conv1 + emb add
    k_stats<<<NN / 64, 256>>>(x, 0, bid, 1);
    k_fin<<<1, 256>>>();
    k_norm<<<NN, 256>>>(x, 0, bid, gn1w, gn1b);
    k_gemm<<<dim3(14, NN / 128), 256>>>(w1);
    k_gather<<<NN / 8, 256>>>(x, w1, out, bid, 0);

    // block 2: gn2 + silu + conv2 + residual
    k_zero_stats<<<8, 256>>>();
    k_stats<<<NN / 64, 256>>>(x, 1, bid, 0);
    k_fin<<<1, 256>>>();
    k_norm<<<NN, 256>>>(x, 1, bid, gn2w, gn2b);
    k_gemm<<<dim3(14, NN / 128), 256>>>(w2);
    k_gather<<<NN / 8, 256>>>(x, w2, out, bid, 1);
}

// round 3
// speedup vs baseline: 3.0823x; 3.0823x over previous
#include <cuda_runtime.h>
#include <cstdint>

// ---------------- problem constants ----------------
#define NN      65536
#define CC      256
#define BB      8
#define EMBD    512
#define NET     7
#define EE      458752
#define WROW    263
#define EPSV    1e-5f

// ---------------- device scratch ----------------
// A in MMA fragment layout: [mt (4096)][kt (32)][lane (32)][4 floats]
__device__ __align__(256) float    g_hA[(size_t)NN * CC];
// B in MMA fragment layout: [t][nt (32)][kt (32)][lane (32)][2 floats]
__device__ __align__(256) float    g_WtB[(size_t)NET * 32 * 32 * 32 * 2];
__device__ __align__(256) float    g_Y[(size_t)NET * NN * CC];
__device__ __align__(256) float    g_out1[(size_t)NN * CC];
__device__ float    g_S1[BB * CC];
__device__ float    g_S2[BB * CC];
__device__ float    g_cnt[BB];
__device__ float    g_mg[BB * 32];
__device__ float    g_istd[BB * 32];
__device__ __align__(256) float    g_emb[BB * CC];
__device__ int      g_deg[NN];
__device__ int      g_off[NN + 1];
__device__ int      g_cur[NN];
__device__ unsigned g_epack[EE];

// ---------------- helpers ----------------
__device__ __forceinline__ unsigned f2tf32(float f) {
    unsigned u;
    asm("cvt.rna.tf32.f32 %0, %1;" : "=r"(u) : "f"(f));
    return u;
}

__device__ __forceinline__ float silu(float y) {
    return y / (1.f + __expf(-y));
}

__device__ __forceinline__ uint32_t smem_u32(const void* p) {
    uint32_t a;
    asm("{ .reg .u64 t; cvta.to.shared.u64 t, %1; cvt.u32.u64 %0, t; }" : "=r"(a) : "l"(p));
    return a;
}

__device__ __forceinline__ void cp16(uint32_t dst, const void* src) {
    asm volatile("cp.async.cg.shared.global [%0], [%1], 16;\n" :: "r"(dst), "l"(src));
}
__device__ __forceinline__ void cp_commit() { asm volatile("cp.async.commit_group;\n" ::: "memory"); }
__device__ __forceinline__ void cp_wait1()  { asm volatile("cp.async.wait_group 1;\n" ::: "memory"); }
__device__ __forceinline__ void cp_wait0()  { asm volatile("cp.async.wait_group 0;\n" ::: "memory"); }

__device__ __forceinline__ void mma_tf32(float c[4], unsigned a0, unsigned a1,
                                         unsigned a2, unsigned a3,
                                         unsigned b0, unsigned b1) {
    asm volatile(
        "mma.sync.aligned.m16n8k8.row.col.f32.tf32.tf32.f32 "
        "{%0,%1,%2,%3}, {%4,%5,%6,%7}, {%8,%9}, {%0,%1,%2,%3};\n"
        : "+f"(c[0]), "+f"(c[1]), "+f"(c[2]), "+f"(c[3])
        : "r"(a0), "r"(a1), "r"(a2), "r"(a3), "r"(b0), "r"(b1));
}

// ---------------- CSR / stats kernels ----------------

__global__ void k_zero_all() {
    int i = blockIdx.x * blockDim.x + threadIdx.x;
    if (i < NN)      g_deg[i] = 0;
    if (i < BB * CC) { g_S1[i] = 0.f; g_S2[i] = 0.f; }
    if (i < BB)      g_cnt[i] = 0.f;
}

__global__ void k_zero_stats() {
    int i = blockIdx.x * blockDim.x + threadIdx.x;
    if (i < BB * CC) { g_S1[i] = 0.f; g_S2[i] = 0.f; }
}

__global__ void k_deg(const int* __restrict__ ei) {
    int e = blockIdx.x * blockDim.x + threadIdx.x;
    if (e < EE) atomicAdd(&g_deg[ei[e]], 1);
}

__global__ void k_scan() {
    __shared__ int ps[1024];
    int t = threadIdx.x;
    int s = 0;
#pragma unroll 8
    for (int i = 0; i < 64; i++) s += g_deg[t * 64 + i];
    ps[t] = s;
    __syncthreads();
    for (int off = 1; off < 1024; off <<= 1) {
        int v = (t >= off) ? ps[t - off] : 0;
        __syncthreads();
        ps[t] += v;
        __syncthreads();
    }
    int run = (t == 0) ? 0 : ps[t - 1];
    for (int i = 0; i < 64; i++) {
        int d = g_deg[t * 64 + i];
        g_off[t * 64 + i] = run;
        g_cur[t * 64 + i] = run;
        run += d;
    }
    if (t == 1023) g_off[NN] = run;
}

__global__ void k_fill(const int* __restrict__ ei, const int* __restrict__ et,
                       const int* __restrict__ ntp) {
    int e = blockIdx.x * blockDim.x + threadIdx.x;
    if (e >= EE) return;
    int r = ei[e];
    int c = ei[EE + e];
    int t = et[e];
    int nt = ntp[c];
    int pos = atomicAdd(&g_cur[r], 1);
    g_epack[pos] = (unsigned)c | ((unsigned)t << 16) | ((unsigned)nt << 19);
}

__global__ void k_emb(const float* __restrict__ emb, const float* __restrict__ ew,
                      const float* __restrict__ eb) {
    __shared__ float se[EMBD];
    int b = blockIdx.x;
    int j = threadIdx.x;
    for (int k = j; k < EMBD; k += 256) se[k] = silu(emb[b * EMBD + k]);
    __syncthreads();
    float acc = eb[j];
#pragma unroll 8
    for (int k = 0; k < EMBD; k++) acc = fmaf(se[k], ew[k * CC + j], acc);
    g_emb[b * CC + j] = acc;
}

__global__ void k_stats(const float* __restrict__ src, int use_out1,
                        const int* __restrict__ bid, int do_cnt) {
    const float* s = use_out1 ? g_out1 : src;
    int c = threadIdx.x;
    int r0 = blockIdx.x * 64;
    float s1 = 0.f, s2 = 0.f;
    int cb = bid[r0];
    int cl = 0;
    for (int i = 0; i < 64; i++) {
        int r = r0 + i;
        int b = bid[r];
        if (b != cb) {
            atomicAdd(&g_S1[cb * CC + c], s1);
            atomicAdd(&g_S2[cb * CC + c], s2);
            if (do_cnt && c == 0) atomicAdd(&g_cnt[cb], (float)cl);
            s1 = 0.f; s2 = 0.f; cl = 0; cb = b;
        }
        float v = s[(size_t)r * CC + c];
        s1 += v;
        s2 = fmaf(v, v, s2);
        cl++;
    }
    atomicAdd(&g_S1[cb * CC + c], s1);
    atomicAdd(&g_S2[cb * CC + c], s2);
    if (do_cnt && c == 0) atomicAdd(&g_cnt[cb], (float)cl);
}

__global__ void k_fin() {
    int t = threadIdx.x;
    int b = t >> 5, g = t & 31;
    float gs1 = 0.f, gs2 = 0.f;
#pragma unroll
    for (int i = 0; i < 8; i++) {
        gs1 += g_S1[b * CC + g * 8 + i];
        gs2 += g_S2[b * CC + g * 8 + i];
    }
    float n = g_cnt[b] * 8.f;
    float inv = 1.f / (n + EPSV);
    float m = gs1 * inv;
    float var = (gs2 - 2.f * m * gs1 + n * m * m) * inv;
    g_mg[b * 32 + g] = m;
    g_istd[b * 32 + g] = rsqrtf(var + EPSV);
}

// norm + silu + tf32-round, written into A-fragment layout.
// block = m-tile (16 rows), 256 threads.
__global__ void k_norm(const float* __restrict__ src, int use_out1,
                       const int* __restrict__ bid, const float* __restrict__ w,
                       const float* __restrict__ bbv) {
    __shared__ float s[16 * 256];
    __shared__ int   rb[16];
    const float* sp = use_out1 ? g_out1 : src;
    int mt = blockIdx.x;
    int tid = threadIdx.x;

    // stage 16 rows coalesced
#pragma unroll
    for (int j = 0; j < 4; j++) {
        int q = j * 256 + tid;            // 0..1023 float4 slots
        int row = q >> 6, cv = (q & 63) * 4;
        *(float4*)&s[row * 256 + cv] = *(const float4*)(sp + (size_t)(mt * 16 + row) * CC + cv);
    }
    if (tid < 16) rb[tid] = bid[mt * 16 + tid];
    __syncthreads();

#pragma unroll
    for (int it = 0; it < 4; it++) {
        int idx = it * 256 + tid;         // 0..1023 = kt*32 + lane
        int kt = idx >> 5, lane = idx & 31;
        int gid = lane >> 2, tig = lane & 3;
        int c0 = kt * 8 + tig, c1 = c0 + 4;
        int b0 = rb[gid], b1 = rb[gid + 8];
        float m0 = g_mg[b0 * 32 + kt], i0 = g_istd[b0 * 32 + kt];
        float m1 = g_mg[b1 * 32 + kt], i1 = g_istd[b1 * 32 + kt];
        float w0 = w[c0], w1 = w[c1], q0 = bbv[c0], q1 = bbv[c1];
        float v00 = silu((s[gid * 256 + c0] - m0) * i0 * w0 + q0);
        float v10 = silu((s[(gid + 8) * 256 + c0] - m1) * i1 * w0 + q0);
        float v01 = silu((s[gid * 256 + c1] - m0) * i0 * w1 + q1);
        float v11 = silu((s[(gid + 8) * 256 + c1] - m1) * i1 * w1 + q1);
        float4 o;
        o.x = __uint_as_float(f2tf32(v00));
        o.y = __uint_as_float(f2tf32(v10));
        o.z = __uint_as_float(f2tf32(v01));
        o.w = __uint_as_float(f2tf32(v11));
        *(float4*)&g_hA[(((size_t)mt * 32 + kt) * 32 + lane) * 4] = o;
    }
}

// W[t][k][n] (dense 256 rows per type) -> B-fragment layout, tf32-rounded
__global__ void k_wt(const float* __restrict__ W) {
    int g = blockIdx.x * blockDim.x + threadIdx.x;
    if (g >= NET * 32 * 32 * 32) return;
    int lane = g & 31, kt = (g >> 5) & 31, nt = (g >> 10) & 31, t = g >> 15;
    int gid = lane >> 2, tig = lane & 3;
    int n = nt * 8 + gid;
    float b0 = W[(size_t)(t * WROW + kt * 8 + tig) * CC + n];
    float b1 = W[(size_t)(t * WROW + kt * 8 + tig + 4) * CC + n];
    float2 o;
    o.x = __uint_as_float(f2tf32(b0));
    o.y = __uint_as_float(f2tf32(b1));
    *(float2*)&g_WtB[(size_t)g * 2] = o;
}

// -------- tf32 mma.sync GEMM, fragment-major smem, cp.async double buffer ----
// CTA 128x128, K=256 in four K=64 chunks. smem: A0|A1|B0|B1 each 32KB.
#define GEMM_SMEM 131072

__device__ __forceinline__ void cpA(float* sA, const float* gA, int mt0, int c, int tid) {
#pragma unroll
    for (int i = 0; i < 8; i++) {
        int v = i * 256 + tid;
        int mt_l = v >> 8, rest = v & 255;
        const float* src = gA + (((size_t)(mt0 + mt_l) * 32 + c * 8 + (rest >> 5)) * 32 + (rest & 31)) * 4;
        cp16(smem_u32(sA + v * 4), src);
    }
}

__device__ __forceinline__ void cpB(float* sB, const float* gB, int c, int tid) {
#pragma unroll
    for (int i = 0; i < 8; i++) {
        int v = i * 256 + tid;
        int nt_l = v >> 7, r = v & 127;
        const float* src = gB + ((size_t)nt_l * 32 + c * 8 + (r >> 4)) * 64 + (r & 15) * 4;
        cp16(smem_u32(sB + v * 4), src);
    }
}

__device__ __forceinline__ void compute_chunk(const float* sA, const float* sB,
                                              float c[2][8][4], int wm, int wn, int lane) {
#pragma unroll
    for (int kt = 0; kt < 8; kt++) {
        float4 a0 = *(const float4*)(sA + ((size_t)((wm * 2 + 0) * 8 + kt) * 32 + lane) * 4);
        float4 a1 = *(const float4*)(sA + ((size_t)((wm * 2 + 1) * 8 + kt) * 32 + lane) * 4);
#pragma unroll
        for (int nn = 0; nn < 8; nn++) {
            float2 b = *(const float2*)(sB + ((size_t)((wn * 8 + nn) * 8 + kt) * 32 + lane) * 2);
            unsigned ub0 = __float_as_uint(b.x), ub1 = __float_as_uint(b.y);
            mma_tf32(c[0][nn], __float_as_uint(a0.x), __float_as_uint(a0.y),
                     __float_as_uint(a0.z), __float_as_uint(a0.w), ub0, ub1);
            mma_tf32(c[1][nn], __float_as_uint(a1.x), __float_as_uint(a1.y),
                     __float_as_uint(a1.z), __float_as_uint(a1.w), ub0, ub1);
        }
    }
}

__global__ void __launch_bounds__(256, 1) k_gemm() {
    extern __shared__ float sm[];
    float* A0 = sm;
    float* A1 = sm + 8192;
    float* B0 = sm + 16384;
    float* B1 = sm + 24576;

    int tid = threadIdx.x;
    int lane = tid & 31, warp = tid >> 5;
    int wm = warp & 3, wn = warp >> 2;
    int t = blockIdx.x >> 1, ntile = blockIdx.x & 1;
    int mt0 = blockIdx.y * 8;        // 8 m16-tiles = 128 rows
    int m0 = mt0 * 16, n0 = ntile * 128;

    const float* gA = g_hA;
    const float* gB = g_WtB + ((size_t)t * 32 + ntile * 16) * 32 * 64;

    float c[2][8][4];
#pragma unroll
    for (int mm = 0; mm < 2; mm++)
#pragma unroll
        for (int nn = 0; nn < 8; nn++)
#pragma unroll
            for (int q = 0; q < 4; q++) c[mm][nn][q] = 0.f;

    cpA(A0, gA, mt0, 0, tid); cpB(B0, gB, 0, tid); cp_commit();
    cpA(A1, gA, mt0, 1, tid); cpB(B1, gB, 1, tid); cp_commit();

    cp_wait1(); __syncthreads();
    compute_chunk(A0, B0, c, wm, wn, lane);
    __syncthreads();
    cpA(A0, gA, mt0, 2, tid); cpB(B0, gB, 2, tid); cp_commit();

    cp_wait1(); __syncthreads();
    compute_chunk(A1, B1, c, wm, wn, lane);
    __syncthreads();
    cpA(A1, gA, mt0, 3, tid); cpB(B1, gB, 3, tid); cp_commit();

    cp_wait1(); __syncthreads();
    compute_chunk(A0, B0, c, wm, wn, lane);

    cp_wait0(); __syncthreads();
    compute_chunk(A1, B1, c, wm, wn, lane);

    // epilogue -> g_Y
    int gid = lane >> 2, tig = lane & 3;
    float* Yb = g_Y + ((size_t)t * NN + m0) * CC + n0;
#pragma unroll
    for (int mm = 0; mm < 2; mm++) {
#pragma unroll
        for (int nn = 0; nn < 8; nn++) {
            int r = wm * 32 + mm * 16 + gid;
            int cc2 = wn * 64 + nn * 8 + tig * 2;
            *(float2*)(Yb + (size_t)r * CC + cc2) = make_float2(c[mm][nn][0], c[mm][nn][1]);
            *(float2*)(Yb + (size_t)(r + 8) * CC + cc2) = make_float2(c[mm][nn][2], c[mm][nn][3]);
        }
    }
}

// warp-per-node gather
__global__ void k_gather(const float* __restrict__ xbase, const float* __restrict__ W,
                         float* __restrict__ dout, const int* __restrict__ bid,
                         int final_pass) {
    int widx = (blockIdx.x * blockDim.x + threadIdx.x) >> 5;
    int lane = threadIdx.x & 31;
    if (widx >= NN) return;
    int n = widx;
    const float* bp;
    float* dst;
    if (final_pass) {
        bp = xbase + (size_t)n * CC;
        dst = dout + (size_t)n * CC;
    } else {
        bp = g_emb + (size_t)bid[n] * CC;
        dst = g_out1 + (size_t)n * CC;
    }
    float4 a0 = *(const float4*)(bp + lane * 8);
    float4 a1 = *(const float4*)(bp + lane * 8 + 4);
    int e0 = g_off[n], e1 = g_off[n + 1];
    for (int e = e0; e < e1; e++) {
        unsigned p = g_epack[e];
        int c = p & 0xFFFF;
        int t = (p >> 16) & 7;
        int nt = (p >> 19) & 7;
        const float* y = g_Y + ((size_t)t * NN + c) * CC + lane * 8;
        const float* wr = W + (size_t)(t * WROW + CC + nt) * CC + lane * 8;
        float4 y0 = *(const float4*)y;
        float4 y1 = *(const float4*)(y + 4);
        float4 w0 = *(const float4*)wr;
        float4 w1 = *(const float4*)(wr + 4);
        a0.x += y0.x + w0.x; a0.y += y0.y + w0.y;
        a0.z += y0.z + w0.z; a0.w += y0.w + w0.w;
        a1.x += y1.x + w1.x; a1.y += y1.y + w1.y;
        a1.z += y1.z + w1.z; a1.w += y1.w + w1.w;
    }
    *(float4*)(dst + lane * 8) = a0;
    *(float4*)(dst + lane * 8 + 4) = a1;
}

// ---------------- launcher ----------------
extern "C" void kernel_launch(void* const* d_in, const int* in_sizes, int n_in,
                              void* d_out, int out_size) {
    const float* x    = (const float*)d_in[0];
    const float* emb  = (const float*)d_in[1];
    const int*   bid  = (const int*)d_in[2];
    const int*   ei   = (const int*)d_in[3];
    const int*   et   = (const int*)d_in[4];
    const int*   ntp  = (const int*)d_in[5];
    const float* gn1w = (const float*)d_in[6];
    const float* gn1b = (const float*)d_in[7];
    const float* w1   = (const float*)d_in[8];
    const float* embw = (const float*)d_in[9];
    const float* embb = (const float*)d_in[10];
    const float* gn2w = (const float*)d_in[11];
    const float* gn2b = (const float*)d_in[12];
    const float* w2   = (const float*)d_in[13];
    float* out = (float*)d_out;

    static int s_attr = 0;
    if (!s_attr) {
        cudaFuncSetAttribute(k_gemm, cudaFuncAttributeMaxDynamicSharedMemorySize, GEMM_SMEM);
        s_attr = 1;
    }

    // CSR build (shared by both convs) + emb
    k_zero_all<<<(NN + 255) / 256, 256>>>();
    k_deg<<<EE / 256, 256>>>(ei);
    k_scan<<<1, 1024>>>();
    k_fill<<<EE / 256, 256>>>(ei, et, ntp);
    k_emb<<<BB, 256>>>(emb, embw, embb);

    // block 1
    k_stats<<<NN / 64, 256>>>(x, 0, bid, 1);
    k_fin<<<1, 256>>>();
    k_norm<<<NN / 16, 256>>>(x, 0, bid, gn1w, gn1b);
    k_wt<<<(NET * 32768 + 255) / 256, 256>>>(w1);
    k_gemm<<<dim3(14, NN / 128), 256, GEMM_SMEM>>>();
    k_gather<<<NN / 8, 256>>>(x, w1, out, bid, 0);

    // block 2
    k_zero_stats<<<8, 256>>>();
    k_stats<<<NN / 64, 256>>>(x, 1, bid, 0);
    k_fin<<<1, 256>>>();
    k_norm<<<NN / 16, 256>>>(x, 1, bid, gn2w, gn2b);
    k_wt<<<(NET * 32768 + 255) / 256, 256>>>(w2);
    k_gemm<<<dim3(14, NN / 128), 256, GEMM_SMEM>>>();
    k_gather<<<NN / 8, 256>>>(x, w2, out, bid, 1);
}